// round 16
// baseline (speedup 1.0000x reference)
#include <cuda_runtime.h>
#include <cuda_bf16.h>
#include <cstdint>

// LI_no_Spike: u[b,f,t] = clip(tau[f],0,1) * u[b,f,t-1] + x[b,f,t], u[.,.,-1]=0
// x: [B,F,T] fp32 row-major (T innermost), tau: [F] fp32, out: [B,F,T] fp32.
//
// Persistent grid-stride (one resident wave: 152 SMs x 8 CTAs) + streaming
// cache hints (__ldcs on x, __stcs on out: both streams are touched exactly
// once, so L2 caching is pure pollution). Per row: weighted Hillis-Steele
// warp scan, float4 per lane, 4 front-batched LDG.E.128.CS (MLP=4), register
// carry across the 4 segments of T=500.

static constexpr int T_CONST = 500;                    // timesteps
static constexpr int NSEG    = (T_CONST + 127) / 128;  // 4 segments of 128

__global__ __launch_bounds__(256)
void li_scan_kernel(const float* __restrict__ x,
                    const float* __restrict__ tau,
                    float* __restrict__ out,
                    int rows, int F) {
    const int lane   = threadIdx.x & 31;
    const int gwarp  = (blockIdx.x * blockDim.x + threadIdx.x) >> 5;
    const int nwarps = (gridDim.x * blockDim.x) >> 5;
    const unsigned FULL = 0xFFFFFFFFu;

    for (int row = gwarp; row < rows; row += nwarps) {
        // Row ratio: clamp tau into [0,1] ("forward" constraint).
        // tau has real reuse (4KB, B=128 rows per f) -> keep cached (__ldg).
        const float a = fminf(fmaxf(__ldg(&tau[row % F]), 0.0f), 1.0f);

        const float* __restrict__ xr   = x   + (size_t)row * T_CONST;
        float*       __restrict__ orow = out + (size_t)row * T_CONST;

        // ---- Front-batched streaming loads: 4 independent LDG.E.128.CS ----
        float4 v[NSEG];
        #pragma unroll
        for (int s = 0; s < NSEG; s++) {
            const int e = s * 128 + 4 * lane;
            v[s] = (e < T_CONST) ? __ldcs(reinterpret_cast<const float4*>(xr + e))
                                 : make_float4(0.f, 0.f, 0.f, 0.f);
        }

        // Powers of a (cheap, overlaps with load latency)
        const float a2   = a * a;
        const float a3   = a2 * a;
        const float a4   = a2 * a2;
        const float a8   = a4 * a4;
        const float a16  = a8 * a8;
        const float a32  = a16 * a16;
        const float a64  = a32 * a32;
        const float a128 = a64 * a64;

        // a^(4*lane): carry weight at this lane
        float a4l = 1.0f;
        if (lane & 1)  a4l *= a4;
        if (lane & 2)  a4l *= a8;
        if (lane & 4)  a4l *= a16;
        if (lane & 8)  a4l *= a32;
        if (lane & 16) a4l *= a64;

        // ---- Scan over segments (register-resident data) ----
        float c = 0.0f;  // recurrence state entering current segment
        #pragma unroll
        for (int s = 0; s < NSEG; s++) {
            const int e = s * 128 + 4 * lane;

            // Lane-local inclusive scan of 4 elements (state-in = 0)
            const float s0 = v[s].x;
            const float s1 = fmaf(a, s0, v[s].y);
            const float s2 = fmaf(a, s1, v[s].z);
            const float s3 = fmaf(a, s2, v[s].w);

            // Warp-level inclusive scan of lane totals with ratio a^4
            float P = s3;
            {
                float t;
                t = __shfl_up_sync(FULL, P, 1);  if (lane >= 1)  P = fmaf(a4,  t, P);
                t = __shfl_up_sync(FULL, P, 2);  if (lane >= 2)  P = fmaf(a8,  t, P);
                t = __shfl_up_sync(FULL, P, 4);  if (lane >= 4)  P = fmaf(a16, t, P);
                t = __shfl_up_sync(FULL, P, 8);  if (lane >= 8)  P = fmaf(a32, t, P);
                t = __shfl_up_sync(FULL, P, 16); if (lane >= 16) P = fmaf(a64, t, P);
            }

            // State entering this lane's 4 elements: C = P_{lane-1} + a^(4l)*c
            float Pprev = __shfl_up_sync(FULL, P, 1);
            if (lane == 0) Pprev = 0.0f;
            const float C = fmaf(a4l, c, Pprev);

            if (e < T_CONST) {
                float4 o;
                o.x = fmaf(a,  C, s0);
                o.y = fmaf(a2, C, s1);
                o.z = fmaf(a3, C, s2);
                o.w = fmaf(a4, C, s3);
                // Streaming store: output is never re-read -> evict-first.
                __stcs(reinterpret_cast<float4*>(orow + e), o);
            }

            // Carry: state after lane 31 = P_31 + a^128 * c
            const float P31 = __shfl_sync(FULL, P, 31);
            c = fmaf(a128, c, P31);
        }
    }
}

extern "C" void kernel_launch(void* const* d_in, const int* in_sizes, int n_in,
                              void* d_out, int out_size) {
    const float* x   = (const float*)d_in[0];   // [B*F, T]
    const float* tau = (const float*)d_in[1];   // [F]
    float* out = (float*)d_out;

    const int F    = in_sizes[1];               // 1024
    const int rows = in_sizes[0] / T_CONST;     // B*F = 131072

    // One resident wave: 152 SMs x 8 CTAs of 256 threads (32 regs/thread).
    const int threads = 256;
    const int blocks  = 152 * 8;                // 1216 persistent CTAs

    li_scan_kernel<<<blocks, threads>>>(x, tau, out, rows, F);
}